// round 16
// baseline (speedup 1.0000x reference)
// Round 16.
//
// R15 post-mortem: persistent GEMM REGRESSED: total 330.5 (GEMM ~237 vs 226).
// Prediction said "if unchanged, packing was already perfect" - it was worse than
// unchanged: the per-tile pipeline restart (prologue loads not overlapped across
// tiles) costs more than the wave-quantization it removed. Theory falsified;
// persistent scheduling abandoned. GEMM is hereby CLOSED at its measured legacy-HMMA
// rate floor (~15 cyc/HMMA/SMSP, f32-acc; confirmed invariant across R4/R6/R9/R15
// configs). Revert to R14's 1024-CTA GEMM (226us, byte-identical).
//
// R16 theory - band kernel (77.8us, L1 69.5%, tensor 28%, issue 29%):
//  (a) Phase 3 currently serializes [flush STS -> barrier -> mma] per chunk with
//      TWO barriers. Double-buffer the K smem planes in phase 3: issue
//      flush(ch+1 -> other buffer) BEFORE compute(ch), one barrier per iteration.
//      STS/cvt work overlaps mma issue; saves ~16 x (flush+barrier) per CTA.
//  (b) Softmax: use all 256 threads (16 cols/thread + 4-lane shfl reduce) instead
//      of 128 threads x 32 cols - halves the serial exp/max/scale loops.
//  Phase 1 keeps R14 structure exactly (its flush already overlaps the QT cp.async
//  wait; both barriers provably required there).
//  smem: K 4 planes (64512) + QT 2 stages (36864) = 101376/CTA; 2 CTA = 202752
//  fits 228KB/SM; regs unchanged -> occupancy still 2 CTA/SM.
//
// Prediction: band 77.8 -> 71..74us; GEMM back to 226; total 319.6 -> 311..316us.
// rel_err ~7.73e-4 (softmax per-thread summation order changes slightly: 16-serial
// + 4-lane shfl vs 32-serial + 2-lane shfl; same math otherwise).
// Post-mortem rule: if band <72 -> (a) worked, consider phase-1 restructure next;
// if band unchanged -> L1 throughput (not serialization) is the binder and band
// is closed too.

#include <cuda_runtime.h>
#include <cuda_bf16.h>
#include <cuda_fp16.h>
#include <cstdint>

#define BATCH 8
#define SLEN  2048
#define DIM   1024
#define WIN   20
#define MTOT  (BATCH * SLEN)

__device__ __half        g_q16 [(size_t)MTOT * DIM];
__device__ __half        g_w16h[(size_t)DIM * DIM];
__device__ __half        g_w16l[(size_t)DIM * DIM];
__device__ __nv_bfloat16 g_qthi[(size_t)MTOT * DIM];
__device__ __nv_bfloat16 g_qtlo[(size_t)MTOT * DIM];

__device__ __forceinline__ uint32_t smem_u32(const void* p) {
    uint32_t a;
    asm("{ .reg .u64 t; cvta.to.shared.u64 t, %1; cvt.u32.u64 %0, t; }" : "=r"(a) : "l"(p));
    return a;
}
#define CP_ASYNC16(sd, gp) \
    asm volatile("cp.async.cg.shared.global [%0], [%1], 16;" :: "r"(sd), "l"(gp) : "memory")
#define CP_COMMIT()   asm volatile("cp.async.commit_group;" ::: "memory")
#define CP_WAIT0()    asm volatile("cp.async.wait_group 0;" ::: "memory")
#define CP_WAIT1()    asm volatile("cp.async.wait_group 1;" ::: "memory")
#define STS128(a, r0, r1, r2, r3) \
    asm volatile("st.shared.v4.b32 [%0], {%1,%2,%3,%4};" \
                 :: "r"(a), "r"(r0), "r"(r1), "r"(r2), "r"(r3) : "memory")

__device__ __forceinline__ void ldsm_x4(uint32_t a, uint32_t& r0, uint32_t& r1,
                                        uint32_t& r2, uint32_t& r3) {
    asm volatile("ldmatrix.sync.aligned.m8n8.x4.shared.b16 {%0,%1,%2,%3}, [%4];"
                 : "=r"(r0), "=r"(r1), "=r"(r2), "=r"(r3) : "r"(a));
}
__device__ __forceinline__ void ldsm_x4_t(uint32_t a, uint32_t& r0, uint32_t& r1,
                                          uint32_t& r2, uint32_t& r3) {
    asm volatile("ldmatrix.sync.aligned.m8n8.x4.trans.shared.b16 {%0,%1,%2,%3}, [%4];"
                 : "=r"(r0), "=r"(r1), "=r"(r2), "=r"(r3) : "r"(a));
}
__device__ __forceinline__ void mma16816(float* c, const uint32_t* a,
                                         uint32_t b0, uint32_t b1) {
    asm volatile(
        "mma.sync.aligned.m16n8k16.row.col.f32.bf16.bf16.f32 "
        "{%0,%1,%2,%3}, {%4,%5,%6,%7}, {%8,%9}, {%0,%1,%2,%3};"
        : "+f"(c[0]), "+f"(c[1]), "+f"(c[2]), "+f"(c[3])
        : "r"(a[0]), "r"(a[1]), "r"(a[2]), "r"(a[3]), "r"(b0), "r"(b1));
}
__device__ __forceinline__ void mma16816h(float* c, const uint32_t* a,
                                          uint32_t b0, uint32_t b1) {
    asm volatile(
        "mma.sync.aligned.m16n8k16.row.col.f32.f16.f16.f32 "
        "{%0,%1,%2,%3}, {%4,%5,%6,%7}, {%8,%9}, {%0,%1,%2,%3};"
        : "+f"(c[0]), "+f"(c[1]), "+f"(c[2]), "+f"(c[3])
        : "r"(a[0]), "r"(a[1]), "r"(a[2]), "r"(a[3]), "r"(b0), "r"(b1));
}

__global__ __launch_bounds__(256) void qhalf_kernel(const float* __restrict__ Q) {
    size_t i = (size_t)blockIdx.x * 256 + threadIdx.x;
    float4 v = ((const float4*)Q)[i];
    ((__half2*)g_q16)[2 * i]     = __floats2half2_rn(v.x, v.y);
    ((__half2*)g_q16)[2 * i + 1] = __floats2half2_rn(v.z, v.w);
}

__global__ void whalf_kernel(const float* __restrict__ W) {
    __shared__ float t[32][33];
    int bx = blockIdx.x * 32;
    int by = blockIdx.y * 32;
    int tx = threadIdx.x, ty0 = threadIdx.y;
#pragma unroll
    for (int i = 0; i < 4; i++) {
        int ty = ty0 + i * 8;
        t[ty][tx] = W[(size_t)(by + ty) * DIM + bx + tx];
    }
    __syncthreads();
#pragma unroll
    for (int i = 0; i < 4; i++) {
        int ty = ty0 + i * 8;
        float v = t[tx][ty];
        __half h = __float2half_rn(v);
        __half l = __float2half_rn(v - __half2float(h));
        size_t o = (size_t)(bx + ty) * DIM + by + tx;
        g_w16h[o] = h;
        g_w16l[o] = l;
    }
}

// ---- fp16 2-term GEMM (validated R14: f32 acc, 3-stage pipeline, grid 1024) ----
#define KC    32
#define GSTR  80
#define GTILE (128 * GSTR)
#define OFF_A  0
#define OFF_BH GTILE
#define OFF_BL (2 * GTILE)
#define STG   (3 * GTILE)
#define NSTAGE 3
#define SMEM_G (NSTAGE * STG)
#define NCHG  (DIM / KC)

__device__ __forceinline__ void load_stage(uint32_t sst, const __half* a,
                                           const __half* bh, const __half* bl,
                                           int kc0, int tid) {
#pragma unroll
    for (int i = 0; i < 2; i++) {
        int flat = tid + i * 256;
        int r = flat >> 2, seg = flat & 3;
        size_t go = (size_t)r * DIM + kc0 + seg * 8;
        uint32_t so = (uint32_t)(r * GSTR + seg * 16);
        CP_ASYNC16(sst + OFF_A + so, a + go);
        CP_ASYNC16(sst + OFF_BH + so, bh + go);
        CP_ASYNC16(sst + OFF_BL + so, bl + go);
    }
}

__global__ __launch_bounds__(256, 2) void qt_gemm_kernel() {
    extern __shared__ __align__(128) char smem[];
    const int tid  = threadIdx.x;
    const int wid  = tid >> 5, lane = tid & 31;
    const int bn   = blockIdx.x * 128;
    const int bm   = blockIdx.y * 128;
    const int wm   = (wid >> 2) * 64;
    const int wn   = (wid & 3) * 32;
    const uint32_t sb = smem_u32(smem);

    const __half* qa = g_q16  + (size_t)bm * DIM;
    const __half* wh = g_w16h + (size_t)bn * DIM;
    const __half* wl = g_w16l + (size_t)bn * DIM;

    float acc[4][4][4];
#pragma unroll
    for (int i = 0; i < 4; i++)
#pragma unroll
        for (int j = 0; j < 4; j++)
#pragma unroll
            for (int k = 0; k < 4; k++) acc[i][j][k] = 0.f;

    const uint32_t lmo = (uint32_t)((lane & 15) * GSTR + (lane >> 4) * 16);

    load_stage(sb + 0 * STG, qa, wh, wl, 0, tid);
    CP_COMMIT();
    load_stage(sb + 1 * STG, qa, wh, wl, KC, tid);
    CP_COMMIT();

    int sidx = 0;
    for (int c = 0; c < NCHG; c++) {
        if (c + 1 < NCHG) CP_WAIT1(); else CP_WAIT0();
        __syncthreads();

        if (c + 2 < NCHG) {
            int ps = sidx + 2; if (ps >= NSTAGE) ps -= NSTAGE;
            load_stage(sb + ps * STG, qa, wh, wl, (c + 2) * KC, tid);
            CP_COMMIT();
        }

        const uint32_t sst = sb + sidx * STG;
        const uint32_t aB = sst + OFF_A + wm * GSTR + lmo;
        const uint32_t bH = sst + OFF_BH + wn * GSTR + lmo;
        const uint32_t bL = sst + OFF_BL + wn * GSTR + lmo;

#pragma unroll
        for (int kk = 0; kk < 2; kk++) {
            const uint32_t ko = kk * 32;
            uint32_t af[4][4], bh2[2][4], bl2[2][4];
#pragma unroll
            for (int mi = 0; mi < 4; mi++)
                ldsm_x4(aB + mi * (16 * GSTR) + ko, af[mi][0], af[mi][1], af[mi][2], af[mi][3]);
#pragma unroll
            for (int ni = 0; ni < 2; ni++)
                ldsm_x4(bH + ni * (16 * GSTR) + ko, bh2[ni][0], bh2[ni][1], bh2[ni][2], bh2[ni][3]);
#pragma unroll
            for (int ni = 0; ni < 2; ni++)
                ldsm_x4(bL + ni * (16 * GSTR) + ko, bl2[ni][0], bl2[ni][1], bl2[ni][2], bl2[ni][3]);
#pragma unroll
            for (int mi = 0; mi < 4; mi++)
#pragma unroll
                for (int g2 = 0; g2 < 4; g2++) {
                    int ni = g2 >> 1, p = g2 & 1;
                    mma16816h(acc[mi][g2], af[mi], bh2[ni][p], bh2[ni][2 + p]);
                }
#pragma unroll
            for (int mi = 0; mi < 4; mi++)
#pragma unroll
                for (int g2 = 0; g2 < 4; g2++) {
                    int ni = g2 >> 1, p = g2 & 1;
                    mma16816h(acc[mi][g2], af[mi], bl2[ni][p], bl2[ni][2 + p]);
                }
        }
        sidx++; if (sidx >= NSTAGE) sidx -= NSTAGE;
    }

    const int qr = lane >> 2, qc = (lane & 3) * 2;
#pragma unroll
    for (int mi = 0; mi < 4; mi++) {
#pragma unroll
        for (int g2 = 0; g2 < 4; g2++) {
            const int col = bn + wn + g2 * 8 + qc;
#pragma unroll
            for (int half = 0; half < 2; half++) {
                const int row = bm + wm + mi * 16 + qr + half * 8;
                float v0 = acc[mi][g2][half * 2], v1 = acc[mi][g2][half * 2 + 1];
                __nv_bfloat16 h0 = __float2bfloat16(v0);
                __nv_bfloat16 h1 = __float2bfloat16(v1);
                __nv_bfloat16 l0 = __float2bfloat16(v0 - __bfloat162float(h0));
                __nv_bfloat16 l1 = __float2bfloat16(v1 - __bfloat162float(h1));
                size_t o = ((size_t)row * DIM + col) / 2;
                ((__nv_bfloat162*)g_qthi)[o] = __halves2bfloat162(h0, h1);
                ((__nv_bfloat162*)g_qtlo)[o] = __halves2bfloat162(l0, l1);
            }
        }
    }
}

// ---- windowed banded attention: K double-buffered in phase 3 -----------------
// smem: KH0 0, KL0 16128, KH1 32256, KL1 48384 | QT stage0 64512, stage1 82944
// S overlays K at 0; PH/PL overlay QT stage0.
#define QB3  64
#define KS3  144
#define SS3  68
#define KBUF  32256u       // size of one K buffer pair region (KH+KL)
#define O3_KH 0u
#define O3_KL 16128u
#define O3_Q0 64512u
#define QSTG  18432u
#define O3_PH 64512u
#define O3_PL 73728u
#define SMEM_B3 101376u

__device__ __forceinline__ void k3_ldg(float4 (&pv)[4][2], const float* __restrict__ keys,
                                       size_t kbase, int q0, int dc, int tid) {
#pragma unroll
    for (int i = 0; i < 4; i++) {
        int flat = tid + i * 256;
        int r = flat >> 3, seg = flat & 7;
        int kr = q0 - 24 + r;
        if (flat < 896 && (unsigned)kr < SLEN) {
            const float4* gp = (const float4*)(keys + kbase + (size_t)kr * DIM + dc + seg * 8);
            pv[i][0] = gp[0];
            pv[i][1] = gp[1];
        } else {
            pv[i][0] = make_float4(0.f, 0.f, 0.f, 0.f);
            pv[i][1] = make_float4(0.f, 0.f, 0.f, 0.f);
        }
    }
}

// Convert registers -> bf16 hi/lo planes at K buffer base kb (0 or KBUF).
__device__ __forceinline__ void k3_flush(const float4 (&pv)[4][2], uint32_t sb,
                                         uint32_t kb, int tid) {
#pragma unroll
    for (int i = 0; i < 4; i++) {
        int flat = tid + i * 256;
        if (flat < 896) {
            int r = flat >> 3, seg = flat & 7;
            uint32_t sh = sb + kb + O3_KH + (uint32_t)(r * KS3 + seg * 16);
            uint32_t sl = sb + kb + O3_KL + (uint32_t)(r * KS3 + seg * 16);
            uint32_t hreg[4], lreg[4];
#pragma unroll
            for (int j = 0; j < 2; j++) {
                float4 v = pv[i][j];
                __nv_bfloat162 h0 = __floats2bfloat162_rn(v.x, v.y);
                __nv_bfloat162 h1 = __floats2bfloat162_rn(v.z, v.w);
                float2 b0 = __bfloat1622float2(h0);
                float2 b1 = __bfloat1622float2(h1);
                __nv_bfloat162 l0 = __floats2bfloat162_rn(v.x - b0.x, v.y - b0.y);
                __nv_bfloat162 l1 = __floats2bfloat162_rn(v.z - b1.x, v.w - b1.y);
                hreg[2 * j]     = *(uint32_t*)&h0;
                hreg[2 * j + 1] = *(uint32_t*)&h1;
                lreg[2 * j]     = *(uint32_t*)&l0;
                lreg[2 * j + 1] = *(uint32_t*)&l1;
            }
            STS128(sh, hreg[0], hreg[1], hreg[2], hreg[3]);
            STS128(sl, lreg[0], lreg[1], lreg[2], lreg[3]);
        }
    }
}

__device__ __forceinline__ void qt_cp(uint32_t qdst, size_t qtbase, int dc, int tid) {
#pragma unroll
    for (int i = 0; i < 2; i++) {
        int flat = tid + i * 256;
        int r = flat >> 3, seg = flat & 7;
        size_t go = qtbase + (size_t)r * DIM + dc + seg * 8;
        uint32_t so = (uint32_t)(r * KS3 + seg * 16);
        CP_ASYNC16(qdst + so, g_qthi + go);
        CP_ASYNC16(qdst + 9216u + so, g_qtlo + go);
    }
}

__global__ __launch_bounds__(256, 2) void band_attn_kernel(const float* __restrict__ keys,
                                                           float* __restrict__ out) {
    extern __shared__ __align__(128) char smem[];
    const uint32_t sb = smem_u32(smem);
    const int tid = threadIdx.x, wid = tid >> 5, lane = tid & 31;
    const int b = blockIdx.y, q0 = blockIdx.x * QB3;
    const size_t kbase  = (size_t)b * SLEN * DIM;
    const size_t qtbase = ((size_t)b * SLEN + q0) * DIM;

    const int g  = wid >> 1;
    const int hw = wid & 1;

    float4 pv[4][2];

    // ---------------- phase 1 (R14 structure, K buffer 0 only) --------------
    float sacc[4][4];
#pragma unroll
    for (int i = 0; i < 4; i++)
#pragma unroll
        for (int j = 0; j < 4; j++) sacc[i][j] = 0.f;

    const uint32_t lmA = (uint32_t)((16 * g + (lane & 15)) * KS3 + (lane >> 4) * 16);
    const uint32_t lmB = (uint32_t)((16 * g + 32 * hw + (lane & 15)) * KS3 + (lane >> 4) * 16);

    k3_ldg(pv, keys, kbase, q0, 0, tid);
    qt_cp(sb + O3_Q0, qtbase, 0, tid);
    CP_COMMIT();

    for (int ch = 0; ch < 16; ch++) {
        const uint32_t qs = sb + O3_Q0 + (uint32_t)(ch & 1) * QSTG;
        k3_flush(pv, sb, 0u, tid);
        if (ch + 1 < 16) {
            qt_cp(sb + O3_Q0 + (uint32_t)((ch + 1) & 1) * QSTG, qtbase, (ch + 1) * 64, tid);
            CP_COMMIT();
            k3_ldg(pv, keys, kbase, q0, (ch + 1) * 64, tid);
            CP_WAIT1();
        } else {
            CP_WAIT0();
        }
        __syncthreads();

#pragma unroll
        for (int ks = 0; ks < 4; ks++) {
            const uint32_t ko = ks * 32;
            uint32_t ah[4], al[4], bh[2][4], bl[2][4];
            ldsm_x4(qs + lmA + ko, ah[0], ah[1], ah[2], ah[3]);
            ldsm_x4(qs + 9216u + lmA + ko, al[0], al[1], al[2], al[3]);
#pragma unroll
            for (int nb = 0; nb < 2; nb++) {
                uint32_t ba = lmB + (uint32_t)(nb * 16 * KS3) + ko;
                ldsm_x4(sb + O3_KH + ba, bh[nb][0], bh[nb][1], bh[nb][2], bh[nb][3]);
                ldsm_x4(sb + O3_KL + ba, bl[nb][0], bl[nb][1], bl[nb][2], bl[nb][3]);
            }
#pragma unroll
            for (int nf = 0; nf < 4; nf++) {
                int nb = nf >> 1, p = nf & 1;
                mma16816(sacc[nf], ah, bh[nb][p], bh[nb][2 + p]);
            }
#pragma unroll
            for (int nf = 0; nf < 4; nf++) {
                int nb = nf >> 1, p = nf & 1;
                mma16816(sacc[nf], ah, bl[nb][p], bl[nb][2 + p]);
            }
#pragma unroll
            for (int nf = 0; nf < 4; nf++) {
                int nb = nf >> 1, p = nf & 1;
                mma16816(sacc[nf], al, bh[nb][p], bh[nb][2 + p]);
            }
        }
        __syncthreads();
    }

    // S fragments -> smem (overlays K region at offset 0)
    {
        float* S = (float*)smem;
        int r0 = 16 * g + (lane >> 2);
        int c0 = 32 * hw + (lane & 3) * 2;
#pragma unroll
        for (int nf = 0; nf < 4; nf++) {
            int c = c0 + nf * 8;
            *(float2*)&S[r0 * SS3 + c]       = make_float2(sacc[nf][0], sacc[nf][1]);
            *(float2*)&S[(r0 + 8) * SS3 + c] = make_float2(sacc[nf][2], sacc[nf][3]);
        }
    }
    __syncthreads();

    // prefetch phase-3 K(0) while softmax runs
    k3_ldg(pv, keys, kbase, q0, 0, tid);

    // ---------------- softmax: all 256 threads, 16 cols each -----------------
    {
        float* S = (float*)smem;
        __nv_bfloat16* PH = (__nv_bfloat16*)(smem + O3_PH);
        __nv_bfloat16* PL = (__nv_bfloat16*)(smem + O3_PL);
        const int row = tid >> 2, part = tid & 3;
        const int rm = row & 15;
        const int w0 = q0 + (row & ~15) - 24;
        int cmin = rm + 4;
        { int t = -w0;            if (t > cmin) cmin = t; }
        int cmax = rm + 44;
        { int t = SLEN - 1 - w0;  if (t < cmax) cmax = t; }
        const int cbeg = part * 16, cend = cbeg + 16;

        float mx = -3.4e38f;
        for (int c = cbeg; c < cend; c++)
            if (c >= cmin && c <= cmax) mx = fmaxf(mx, S[row * SS3 + c]);
        mx = fmaxf(mx, __shfl_xor_sync(0xFFFFFFFFu, mx, 1));
        mx = fmaxf(mx, __shfl_xor_sync(0xFFFFFFFFu, mx, 2));

        float sum = 0.f;
        for (int c = cbeg; c < cend; c++) {
            float e = (c >= cmin && c <= cmax) ? __expf(S[row * SS3 + c] - mx) : 0.f;
            S[row * SS3 + c] = e;
            sum += e;
        }
        sum += __shfl_xor_sync(0xFFFFFFFFu, sum, 1);
        sum += __shfl_xor_sync(0xFFFFFFFFu, sum, 2);
        const float inv = 1.f / sum;

        for (int c = cbeg; c < cend; c++) {
            float p = S[row * SS3 + c] * inv;
            __nv_bfloat16 h = __float2bfloat16(p);
            __nv_bfloat16 l = __float2bfloat16(p - __bfloat162float(h));
            PH[row * 72 + c] = h;
            PL[row * 72 + c] = l;
        }
    }
    __syncthreads();

    // ---------------- phase 3: K double-buffered, one barrier/iter -----------
    const uint32_t lmP = (uint32_t)((16 * g + (lane & 15)) * KS3 + (lane >> 4) * 16);

    // prologue: flush K(0) into buf0, prefetch K(1)
    k3_flush(pv, sb, 0u, tid);
    k3_ldg(pv, keys, kbase, q0, 64, tid);
    __syncthreads();

    for (int ch = 0; ch < 16; ch++) {
        const int dc = ch * 64;
        const uint32_t kb = (uint32_t)(ch & 1) * KBUF;

        // overlap: flush K(ch+1) into the OTHER buffer before compute(ch)
        if (ch + 1 < 16) {
            k3_flush(pv, sb, (uint32_t)((ch + 1) & 1) * KBUF, tid);
            if (ch + 2 < 16)
                k3_ldg(pv, keys, kbase, q0, (ch + 2) * 64, tid);
        }

        float oacc[4][4];
#pragma unroll
        for (int i = 0; i < 4; i++)
#pragma unroll
            for (int j = 0; j < 4; j++) oacc[i][j] = 0.f;

#pragma unroll
        for (int ks = 0; ks < 4; ks++) {
            const uint32_t ko = ks * 32;
            uint32_t ah[4], al[4], bh[2][4], bl[2][4];
            ldsm_x4(sb + O3_PH + lmP + ko, ah[0], ah[1], ah[2], ah[3]);
            ldsm_x4(sb + O3_PL + lmP + ko, al[0], al[1], al[2], al[3]);
#pragma unroll
            for (int ds = 0; ds < 2; ds++) {
                uint32_t ba = (uint32_t)((16 * g + ks * 16 + (lane & 15)) * KS3 +
                                         64 * hw + ds * 32 + (lane >> 4) * 16);
                ldsm_x4_t(sb + kb + O3_KH + ba, bh[ds][0], bh[ds][1], bh[ds][2], bh[ds][3]);
                ldsm_x4_t(sb + kb + O3_KL + ba, bl[ds][0], bl[ds][1], bl[ds][2], bl[ds][3]);
            }
#pragma unroll
            for (int nf = 0; nf < 4; nf++) {
                int ds = nf >> 1, p = nf & 1;
                mma16816(oacc[nf], ah, bh[ds][2 * p], bh[ds][2 * p + 1]);
            }
#pragma unroll
            for (int nf = 0; nf < 4; nf++) {
                int ds = nf >> 1, p = nf & 1;
                mma16816(oacc[nf], ah, bl[ds][2 * p], bl[ds][2 * p + 1]);
            }
#pragma unroll
            for (int nf = 0; nf < 4; nf++) {
                int ds = nf >> 1, p = nf & 1;
                mma16816(oacc[nf], al, bh[ds][2 * p], bh[ds][2 * p + 1]);
            }
        }

        const int r0 = q0 + 16 * g + (lane >> 2);
        const int c0 = dc + 32 * hw + (lane & 3) * 2;
#pragma unroll
        for (int nf = 0; nf < 4; nf++) {
            int c = c0 + nf * 8;
            *(float2*)(out + kbase + (size_t)r0 * DIM + c) =
                make_float2(oacc[nf][0], oacc[nf][1]);
            *(float2*)(out + kbase + (size_t)(r0 + 8) * DIM + c) =
                make_float2(oacc[nf][2], oacc[nf][3]);
        }
        __syncthreads();   // flush(ch+1) visible; compute(ch) done before buf reuse
    }
}

extern "C" void kernel_launch(void* const* d_in, const int* in_sizes, int n_in,
                              void* d_out, int out_size) {
    const float* queries = (const float*)d_in[0];
    const float* keys    = (const float*)d_in[1];
    const float* W       = (const float*)d_in[2];
    // d_in[3] = b_reduce: per-(b,q) constant added to all logits -> softmax-invariant, unused.
    float* out = (float*)d_out;

    cudaFuncSetAttribute(qt_gemm_kernel, cudaFuncAttributeMaxDynamicSharedMemorySize, SMEM_G);
    cudaFuncSetAttribute(band_attn_kernel, cudaFuncAttributeMaxDynamicSharedMemorySize, SMEM_B3);

    const int elemGrid = (MTOT * DIM) / 4 / 256;
    qhalf_kernel<<<elemGrid, 256>>>(queries);
    whalf_kernel<<<dim3(DIM / 32, DIM / 32), dim3(32, 8)>>>(W);

    dim3 gg(DIM / 128, MTOT / 128);
    qt_gemm_kernel<<<gg, 256, SMEM_G>>>();

    dim3 g2(SLEN / QB3, BATCH);
    band_attn_kernel<<<g2, 256, SMEM_B3>>>(keys, out);
}

// round 17
// speedup vs baseline: 1.0580x; 1.0580x over previous
// Round 17.
//
// R16 post-mortem: band double-buffer REGRESSED (band 77.8 -> 91.3us, total 336.4).
// Root cause on re-analysis: issue is IN-ORDER per warp, so placing flush(ch+1)
// (whose STS consumes LDG data fetched only ONE iteration earlier) ahead of
// compute(ch) put the LDG long-scoreboard stall directly in front of the mma
// stream instead of hiding it behind a full compute phase as R14's ordering did.
// The extra 32KB smem and register pressure added nothing. Theory falsified.
//
// Standing conclusions after 16 rounds of measurement:
//  - GEMM closed: legacy HMMA f32-acc runs ~15 cyc/HMMA/SMSP on sm_103a,
//    invariant to pipelining (R9 neutral), persistence (R15 regressed),
//    precision tricks (int8 4.5x slower R5, fp16-acc inaccurate R13).
//    fp16 2-term / 226us is the floor on this toolchain (tcgen05 is
//    ptxas-blocked at plain compute_103).
//  - Band closed: both restructures of the 77.8us kernel (R7/8 windowing WON,
//    R16 pipelining LOST); remaining L1-bound mixed profile has ~5-10us of
//    theoretical headroom not reachable by barrier/buffering games.
//
// R17 = exact revert to the R14 optimum (measured 319.6us, rel_err 7.7306e-4).
// Prediction: 319.6 +- 2us, rel_err exactly 0.0007730557. This locks in the
// best-known configuration: 3.6x over the fp32 baseline (1136.7 -> 319.6).

#include <cuda_runtime.h>
#include <cuda_bf16.h>
#include <cuda_fp16.h>
#include <cstdint>

#define BATCH 8
#define SLEN  2048
#define DIM   1024
#define WIN   20
#define MTOT  (BATCH * SLEN)

__device__ __half        g_q16 [(size_t)MTOT * DIM];
__device__ __half        g_w16h[(size_t)DIM * DIM];
__device__ __half        g_w16l[(size_t)DIM * DIM];
__device__ __nv_bfloat16 g_qthi[(size_t)MTOT * DIM];
__device__ __nv_bfloat16 g_qtlo[(size_t)MTOT * DIM];

__device__ __forceinline__ uint32_t smem_u32(const void* p) {
    uint32_t a;
    asm("{ .reg .u64 t; cvta.to.shared.u64 t, %1; cvt.u32.u64 %0, t; }" : "=r"(a) : "l"(p));
    return a;
}
#define CP_ASYNC16(sd, gp) \
    asm volatile("cp.async.cg.shared.global [%0], [%1], 16;" :: "r"(sd), "l"(gp) : "memory")
#define CP_COMMIT()   asm volatile("cp.async.commit_group;" ::: "memory")
#define CP_WAIT0()    asm volatile("cp.async.wait_group 0;" ::: "memory")
#define CP_WAIT1()    asm volatile("cp.async.wait_group 1;" ::: "memory")
#define STS128(a, r0, r1, r2, r3) \
    asm volatile("st.shared.v4.b32 [%0], {%1,%2,%3,%4};" \
                 :: "r"(a), "r"(r0), "r"(r1), "r"(r2), "r"(r3) : "memory")

__device__ __forceinline__ void ldsm_x4(uint32_t a, uint32_t& r0, uint32_t& r1,
                                        uint32_t& r2, uint32_t& r3) {
    asm volatile("ldmatrix.sync.aligned.m8n8.x4.shared.b16 {%0,%1,%2,%3}, [%4];"
                 : "=r"(r0), "=r"(r1), "=r"(r2), "=r"(r3) : "r"(a));
}
__device__ __forceinline__ void ldsm_x4_t(uint32_t a, uint32_t& r0, uint32_t& r1,
                                          uint32_t& r2, uint32_t& r3) {
    asm volatile("ldmatrix.sync.aligned.m8n8.x4.trans.shared.b16 {%0,%1,%2,%3}, [%4];"
                 : "=r"(r0), "=r"(r1), "=r"(r2), "=r"(r3) : "r"(a));
}
__device__ __forceinline__ void mma16816(float* c, const uint32_t* a,
                                         uint32_t b0, uint32_t b1) {
    asm volatile(
        "mma.sync.aligned.m16n8k16.row.col.f32.bf16.bf16.f32 "
        "{%0,%1,%2,%3}, {%4,%5,%6,%7}, {%8,%9}, {%0,%1,%2,%3};"
        : "+f"(c[0]), "+f"(c[1]), "+f"(c[2]), "+f"(c[3])
        : "r"(a[0]), "r"(a[1]), "r"(a[2]), "r"(a[3]), "r"(b0), "r"(b1));
}
__device__ __forceinline__ void mma16816h(float* c, const uint32_t* a,
                                          uint32_t b0, uint32_t b1) {
    asm volatile(
        "mma.sync.aligned.m16n8k16.row.col.f32.f16.f16.f32 "
        "{%0,%1,%2,%3}, {%4,%5,%6,%7}, {%8,%9}, {%0,%1,%2,%3};"
        : "+f"(c[0]), "+f"(c[1]), "+f"(c[2]), "+f"(c[3])
        : "r"(a[0]), "r"(a[1]), "r"(a[2]), "r"(a[3]), "r"(b0), "r"(b1));
}

__global__ __launch_bounds__(256) void qhalf_kernel(const float* __restrict__ Q) {
    size_t i = (size_t)blockIdx.x * 256 + threadIdx.x;
    float4 v = ((const float4*)Q)[i];
    ((__half2*)g_q16)[2 * i]     = __floats2half2_rn(v.x, v.y);
    ((__half2*)g_q16)[2 * i + 1] = __floats2half2_rn(v.z, v.w);
}

__global__ void whalf_kernel(const float* __restrict__ W) {
    __shared__ float t[32][33];
    int bx = blockIdx.x * 32;
    int by = blockIdx.y * 32;
    int tx = threadIdx.x, ty0 = threadIdx.y;
#pragma unroll
    for (int i = 0; i < 4; i++) {
        int ty = ty0 + i * 8;
        t[ty][tx] = W[(size_t)(by + ty) * DIM + bx + tx];
    }
    __syncthreads();
#pragma unroll
    for (int i = 0; i < 4; i++) {
        int ty = ty0 + i * 8;
        float v = t[tx][ty];
        __half h = __float2half_rn(v);
        __half l = __float2half_rn(v - __half2float(h));
        size_t o = (size_t)(bx + ty) * DIM + by + tx;
        g_w16h[o] = h;
        g_w16l[o] = l;
    }
}

// ---- fp16 2-term GEMM (validated R14: f32 acc, 3-stage pipeline, grid 1024) ----
#define KC    32
#define GSTR  80
#define GTILE (128 * GSTR)
#define OFF_A  0
#define OFF_BH GTILE
#define OFF_BL (2 * GTILE)
#define STG   (3 * GTILE)
#define NSTAGE 3
#define SMEM_G (NSTAGE * STG)
#define NCHG  (DIM / KC)

__device__ __forceinline__ void load_stage(uint32_t sst, const __half* a,
                                           const __half* bh, const __half* bl,
                                           int kc0, int tid) {
#pragma unroll
    for (int i = 0; i < 2; i++) {
        int flat = tid + i * 256;
        int r = flat >> 2, seg = flat & 3;
        size_t go = (size_t)r * DIM + kc0 + seg * 8;
        uint32_t so = (uint32_t)(r * GSTR + seg * 16);
        CP_ASYNC16(sst + OFF_A + so, a + go);
        CP_ASYNC16(sst + OFF_BH + so, bh + go);
        CP_ASYNC16(sst + OFF_BL + so, bl + go);
    }
}

__global__ __launch_bounds__(256, 2) void qt_gemm_kernel() {
    extern __shared__ __align__(128) char smem[];
    const int tid  = threadIdx.x;
    const int wid  = tid >> 5, lane = tid & 31;
    const int bn   = blockIdx.x * 128;
    const int bm   = blockIdx.y * 128;
    const int wm   = (wid >> 2) * 64;
    const int wn   = (wid & 3) * 32;
    const uint32_t sb = smem_u32(smem);

    const __half* qa = g_q16  + (size_t)bm * DIM;
    const __half* wh = g_w16h + (size_t)bn * DIM;
    const __half* wl = g_w16l + (size_t)bn * DIM;

    float acc[4][4][4];
#pragma unroll
    for (int i = 0; i < 4; i++)
#pragma unroll
        for (int j = 0; j < 4; j++)
#pragma unroll
            for (int k = 0; k < 4; k++) acc[i][j][k] = 0.f;

    const uint32_t lmo = (uint32_t)((lane & 15) * GSTR + (lane >> 4) * 16);

    load_stage(sb + 0 * STG, qa, wh, wl, 0, tid);
    CP_COMMIT();
    load_stage(sb + 1 * STG, qa, wh, wl, KC, tid);
    CP_COMMIT();

    int sidx = 0;
    for (int c = 0; c < NCHG; c++) {
        if (c + 1 < NCHG) CP_WAIT1(); else CP_WAIT0();
        __syncthreads();

        if (c + 2 < NCHG) {
            int ps = sidx + 2; if (ps >= NSTAGE) ps -= NSTAGE;
            load_stage(sb + ps * STG, qa, wh, wl, (c + 2) * KC, tid);
            CP_COMMIT();
        }

        const uint32_t sst = sb + sidx * STG;
        const uint32_t aB = sst + OFF_A + wm * GSTR + lmo;
        const uint32_t bH = sst + OFF_BH + wn * GSTR + lmo;
        const uint32_t bL = sst + OFF_BL + wn * GSTR + lmo;

#pragma unroll
        for (int kk = 0; kk < 2; kk++) {
            const uint32_t ko = kk * 32;
            uint32_t af[4][4], bh2[2][4], bl2[2][4];
#pragma unroll
            for (int mi = 0; mi < 4; mi++)
                ldsm_x4(aB + mi * (16 * GSTR) + ko, af[mi][0], af[mi][1], af[mi][2], af[mi][3]);
#pragma unroll
            for (int ni = 0; ni < 2; ni++)
                ldsm_x4(bH + ni * (16 * GSTR) + ko, bh2[ni][0], bh2[ni][1], bh2[ni][2], bh2[ni][3]);
#pragma unroll
            for (int ni = 0; ni < 2; ni++)
                ldsm_x4(bL + ni * (16 * GSTR) + ko, bl2[ni][0], bl2[ni][1], bl2[ni][2], bl2[ni][3]);
#pragma unroll
            for (int mi = 0; mi < 4; mi++)
#pragma unroll
                for (int g2 = 0; g2 < 4; g2++) {
                    int ni = g2 >> 1, p = g2 & 1;
                    mma16816h(acc[mi][g2], af[mi], bh2[ni][p], bh2[ni][2 + p]);
                }
#pragma unroll
            for (int mi = 0; mi < 4; mi++)
#pragma unroll
                for (int g2 = 0; g2 < 4; g2++) {
                    int ni = g2 >> 1, p = g2 & 1;
                    mma16816h(acc[mi][g2], af[mi], bl2[ni][p], bl2[ni][2 + p]);
                }
        }
        sidx++; if (sidx >= NSTAGE) sidx -= NSTAGE;
    }

    const int qr = lane >> 2, qc = (lane & 3) * 2;
#pragma unroll
    for (int mi = 0; mi < 4; mi++) {
#pragma unroll
        for (int g2 = 0; g2 < 4; g2++) {
            const int col = bn + wn + g2 * 8 + qc;
#pragma unroll
            for (int half = 0; half < 2; half++) {
                const int row = bm + wm + mi * 16 + qr + half * 8;
                float v0 = acc[mi][g2][half * 2], v1 = acc[mi][g2][half * 2 + 1];
                __nv_bfloat16 h0 = __float2bfloat16(v0);
                __nv_bfloat16 h1 = __float2bfloat16(v1);
                __nv_bfloat16 l0 = __float2bfloat16(v0 - __bfloat162float(h0));
                __nv_bfloat16 l1 = __float2bfloat16(v1 - __bfloat162float(h1));
                size_t o = ((size_t)row * DIM + col) / 2;
                ((__nv_bfloat162*)g_qthi)[o] = __halves2bfloat162(h0, h1);
                ((__nv_bfloat162*)g_qtlo)[o] = __halves2bfloat162(l0, l1);
            }
        }
    }
}

// ---- windowed banded attention (validated R14: in-kernel K conversion) ----
#define QB3  64
#define KS3  144
#define SS3  68

#define O3_KH 0u
#define O3_KL 16128u
#define O3_Q0 32256u
#define QSTG  18432u
#define O3_PH 32256u
#define O3_PL 41472u
#define SMEM_B3 69120u

__device__ __forceinline__ void k3_ldg(float4 (&pv)[4][2], const float* __restrict__ keys,
                                       size_t kbase, int q0, int dc, int tid) {
#pragma unroll
    for (int i = 0; i < 4; i++) {
        int flat = tid + i * 256;
        int r = flat >> 3, seg = flat & 7;
        int kr = q0 - 24 + r;
        if (flat < 896 && (unsigned)kr < SLEN) {
            const float4* gp = (const float4*)(keys + kbase + (size_t)kr * DIM + dc + seg * 8);
            pv[i][0] = gp[0];
            pv[i][1] = gp[1];
        } else {
            pv[i][0] = make_float4(0.f, 0.f, 0.f, 0.f);
            pv[i][1] = make_float4(0.f, 0.f, 0.f, 0.f);
        }
    }
}

__device__ __forceinline__ void k3_flush(const float4 (&pv)[4][2], uint32_t sb, int tid) {
#pragma unroll
    for (int i = 0; i < 4; i++) {
        int flat = tid + i * 256;
        if (flat < 896) {
            int r = flat >> 3, seg = flat & 7;
            uint32_t sh = sb + O3_KH + (uint32_t)(r * KS3 + seg * 16);
            uint32_t sl = sb + O3_KL + (uint32_t)(r * KS3 + seg * 16);
            uint32_t hreg[4], lreg[4];
#pragma unroll
            for (int j = 0; j < 2; j++) {
                float4 v = pv[i][j];
                __nv_bfloat162 h0 = __floats2bfloat162_rn(v.x, v.y);
                __nv_bfloat162 h1 = __floats2bfloat162_rn(v.z, v.w);
                float2 b0 = __bfloat1622float2(h0);
                float2 b1 = __bfloat1622float2(h1);
                __nv_bfloat162 l0 = __floats2bfloat162_rn(v.x - b0.x, v.y - b0.y);
                __nv_bfloat162 l1 = __floats2bfloat162_rn(v.z - b1.x, v.w - b1.y);
                hreg[2 * j]     = *(uint32_t*)&h0;
                hreg[2 * j + 1] = *(uint32_t*)&h1;
                lreg[2 * j]     = *(uint32_t*)&l0;
                lreg[2 * j + 1] = *(uint32_t*)&l1;
            }
            STS128(sh, hreg[0], hreg[1], hreg[2], hreg[3]);
            STS128(sl, lreg[0], lreg[1], lreg[2], lreg[3]);
        }
    }
}

__device__ __forceinline__ void qt_cp(uint32_t qdst, size_t qtbase, int dc, int tid) {
#pragma unroll
    for (int i = 0; i < 2; i++) {
        int flat = tid + i * 256;
        int r = flat >> 3, seg = flat & 7;
        size_t go = qtbase + (size_t)r * DIM + dc + seg * 8;
        uint32_t so = (uint32_t)(r * KS3 + seg * 16);
        CP_ASYNC16(qdst + so, g_qthi + go);
        CP_ASYNC16(qdst + 9216u + so, g_qtlo + go);
    }
}

__global__ __launch_bounds__(256, 2) void band_attn_kernel(const float* __restrict__ keys,
                                                           float* __restrict__ out) {
    extern __shared__ __align__(128) char smem[];
    const uint32_t sb = smem_u32(smem);
    const int tid = threadIdx.x, wid = tid >> 5, lane = tid & 31;
    const int b = blockIdx.y, q0 = blockIdx.x * QB3;
    const size_t kbase  = (size_t)b * SLEN * DIM;
    const size_t qtbase = ((size_t)b * SLEN + q0) * DIM;

    const int g  = wid >> 1;
    const int hw = wid & 1;

    float4 pv[4][2];

    float sacc[4][4];
#pragma unroll
    for (int i = 0; i < 4; i++)
#pragma unroll
        for (int j = 0; j < 4; j++) sacc[i][j] = 0.f;

    const uint32_t lmA = (uint32_t)((16 * g + (lane & 15)) * KS3 + (lane >> 4) * 16);
    const uint32_t lmB = (uint32_t)((16 * g + 32 * hw + (lane & 15)) * KS3 + (lane >> 4) * 16);

    k3_ldg(pv, keys, kbase, q0, 0, tid);
    qt_cp(sb + O3_Q0, qtbase, 0, tid);
    CP_COMMIT();

    for (int ch = 0; ch < 16; ch++) {
        const uint32_t qs = sb + O3_Q0 + (uint32_t)(ch & 1) * QSTG;
        k3_flush(pv, sb, tid);
        if (ch + 1 < 16) {
            qt_cp(sb + O3_Q0 + (uint32_t)((ch + 1) & 1) * QSTG, qtbase, (ch + 1) * 64, tid);
            CP_COMMIT();
            k3_ldg(pv, keys, kbase, q0, (ch + 1) * 64, tid);
            CP_WAIT1();
        } else {
            CP_WAIT0();
        }
        __syncthreads();

#pragma unroll
        for (int ks = 0; ks < 4; ks++) {
            const uint32_t ko = ks * 32;
            uint32_t ah[4], al[4], bh[2][4], bl[2][4];
            ldsm_x4(qs + lmA + ko, ah[0], ah[1], ah[2], ah[3]);
            ldsm_x4(qs + 9216u + lmA + ko, al[0], al[1], al[2], al[3]);
#pragma unroll
            for (int nb = 0; nb < 2; nb++) {
                uint32_t ba = lmB + (uint32_t)(nb * 16 * KS3) + ko;
                ldsm_x4(sb + O3_KH + ba, bh[nb][0], bh[nb][1], bh[nb][2], bh[nb][3]);
                ldsm_x4(sb + O3_KL + ba, bl[nb][0], bl[nb][1], bl[nb][2], bl[nb][3]);
            }
#pragma unroll
            for (int nf = 0; nf < 4; nf++) {
                int nb = nf >> 1, p = nf & 1;
                mma16816(sacc[nf], ah, bh[nb][p], bh[nb][2 + p]);
            }
#pragma unroll
            for (int nf = 0; nf < 4; nf++) {
                int nb = nf >> 1, p = nf & 1;
                mma16816(sacc[nf], ah, bl[nb][p], bl[nb][2 + p]);
            }
#pragma unroll
            for (int nf = 0; nf < 4; nf++) {
                int nb = nf >> 1, p = nf & 1;
                mma16816(sacc[nf], al, bh[nb][p], bh[nb][2 + p]);
            }
        }
        __syncthreads();
    }

    // S fragments -> smem (S overlays the K region at offset 0)
    {
        float* S = (float*)smem;
        int r0 = 16 * g + (lane >> 2);
        int c0 = 32 * hw + (lane & 3) * 2;
#pragma unroll
        for (int nf = 0; nf < 4; nf++) {
            int c = c0 + nf * 8;
            *(float2*)&S[r0 * SS3 + c]       = make_float2(sacc[nf][0], sacc[nf][1]);
            *(float2*)&S[(r0 + 8) * SS3 + c] = make_float2(sacc[nf][2], sacc[nf][3]);
        }
    }
    __syncthreads();

    // prefetch phase-3 K(0) while softmax runs
    k3_ldg(pv, keys, kbase, q0, 0, tid);

    if (tid < 128) {
        float* S = (float*)smem;
        __nv_bfloat16* PH = (__nv_bfloat16*)(smem + O3_PH);
        __nv_bfloat16* PL = (__nv_bfloat16*)(smem + O3_PL);
        const int row = tid >> 1, half = tid & 1;
        const int rm = row & 15;
        const int w0 = q0 + (row & ~15) - 24;
        int cmin = rm + 4;
        { int t = -w0;            if (t > cmin) cmin = t; }
        int cmax = rm + 44;
        { int t = SLEN - 1 - w0;  if (t < cmax) cmax = t; }
        const int cbeg = half * 32, cend = cbeg + 32;

        float mx = -3.4e38f;
        for (int c = cbeg; c < cend; c++)
            if (c >= cmin && c <= cmax) mx = fmaxf(mx, S[row * SS3 + c]);
        mx = fmaxf(mx, __shfl_xor_sync(0xFFFFFFFFu, mx, 1));

        float sum = 0.f;
        for (int c = cbeg; c < cend; c++) {
            float e = (c >= cmin && c <= cmax) ? __expf(S[row * SS3 + c] - mx) : 0.f;
            S[row * SS3 + c] = e;
            sum += e;
        }
        sum += __shfl_xor_sync(0xFFFFFFFFu, sum, 1);
        const float inv = 1.f / sum;

        for (int c = cbeg; c < cend; c++) {
            float p = S[row * SS3 + c] * inv;
            __nv_bfloat16 h = __float2bfloat16(p);
            __nv_bfloat16 l = __float2bfloat16(p - __bfloat162float(h));
            PH[row * 72 + c] = h;
            PL[row * 72 + c] = l;
        }
    }
    __syncthreads();

    const uint32_t lmP = (uint32_t)((16 * g + (lane & 15)) * KS3 + (lane >> 4) * 16);
    for (int ch = 0; ch < 16; ch++) {
        const int dc = ch * 64;
        k3_flush(pv, sb, tid);
        if (ch + 1 < 16)
            k3_ldg(pv, keys, kbase, q0, (ch + 1) * 64, tid);
        __syncthreads();

        float oacc[4][4];
#pragma unroll
        for (int i = 0; i < 4; i++)
#pragma unroll
            for (int j = 0; j < 4; j++) oacc[i][j] = 0.f;

#pragma unroll
        for (int ks = 0; ks < 4; ks++) {
            const uint32_t ko = ks * 32;
            uint32_t ah[4], al[4], bh[2][4], bl[2][4];
            ldsm_x4(sb + O3_PH + lmP + ko, ah[0], ah[1], ah[2], ah[3]);
            ldsm_x4(sb + O3_PL + lmP + ko, al[0], al[1], al[2], al[3]);
#pragma unroll
            for (int ds = 0; ds < 2; ds++) {
                uint32_t ba = (uint32_t)((16 * g + ks * 16 + (lane & 15)) * KS3 +
                                         64 * hw + ds * 32 + (lane >> 4) * 16);
                ldsm_x4_t(sb + O3_KH + ba, bh[ds][0], bh[ds][1], bh[ds][2], bh[ds][3]);
                ldsm_x4_t(sb + O3_KL + ba, bl[ds][0], bl[ds][1], bl[ds][2], bl[ds][3]);
            }
#pragma unroll
            for (int nf = 0; nf < 4; nf++) {
                int ds = nf >> 1, p = nf & 1;
                mma16816(oacc[nf], ah, bh[ds][2 * p], bh[ds][2 * p + 1]);
            }
#pragma unroll
            for (int nf = 0; nf < 4; nf++) {
                int ds = nf >> 1, p = nf & 1;
                mma16816(oacc[nf], ah, bl[ds][2 * p], bl[ds][2 * p + 1]);
            }
#pragma unroll
            for (int nf = 0; nf < 4; nf++) {
                int ds = nf >> 1, p = nf & 1;
                mma16816(oacc[nf], al, bh[ds][2 * p], bh[ds][2 * p + 1]);
            }
        }

        const int r0 = q0 + 16 * g + (lane >> 2);
        const int c0 = dc + 32 * hw + (lane & 3) * 2;
#pragma unroll
        for (int nf = 0; nf < 4; nf++) {
            int c = c0 + nf * 8;
            *(float2*)(out + kbase + (size_t)r0 * DIM + c) =
                make_float2(oacc[nf][0], oacc[nf][1]);
            *(float2*)(out + kbase + (size_t)(r0 + 8) * DIM + c) =
                make_float2(oacc[nf][2], oacc[nf][3]);
        }
        __syncthreads();
    }
}

extern "C" void kernel_launch(void* const* d_in, const int* in_sizes, int n_in,
                              void* d_out, int out_size) {
    const float* queries = (const float*)d_in[0];
    const float* keys    = (const float*)d_in[1];
    const float* W       = (const float*)d_in[2];
    // d_in[3] = b_reduce: per-(b,q) constant added to all logits -> softmax-invariant, unused.
    float* out = (float*)d_out;

    cudaFuncSetAttribute(qt_gemm_kernel, cudaFuncAttributeMaxDynamicSharedMemorySize, SMEM_G);
    cudaFuncSetAttribute(band_attn_kernel, cudaFuncAttributeMaxDynamicSharedMemorySize, SMEM_B3);

    const int elemGrid = (MTOT * DIM) / 4 / 256;
    qhalf_kernel<<<elemGrid, 256>>>(queries);
    whalf_kernel<<<dim3(DIM / 32, DIM / 32), dim3(32, 8)>>>(W);

    dim3 gg(DIM / 128, MTOT / 128);
    qt_gemm_kernel<<<gg, 256, SMEM_G>>>();

    dim3 g2(SLEN / QB3, BATCH);
    band_attn_kernel<<<g2, 256, SMEM_B3>>>(keys, out);
}